// round 14
// baseline (speedup 1.0000x reference)
#include <cuda_runtime.h>
#include <math.h>
#include <stdint.h>

// TransformationRotationLoss — persistent CTAs + cp.async.bulk pipeline.
// Deepest-pipeline variant: 1 CTA/SM (grid 148), 512 threads, 4 stages of
// 2048-row (24.5KB/input) tiles = 196KB smem, 4 tiles in flight per TMA stream.
//   u_ta = (SA*b - SB*a) * rsqrt(r1*r2)
//   u_tb = (c-1)*( a*(SA/r1 - e*f/D) + b*(f/D) ), e=d/r1, f=SB-SA*e, D=r2-d*e

#define ALPHA 0.7f
#define BETTA 0.3f

static constexpr int THREADS    = 512;
static constexpr int STAGES     = 4;
static constexpr int TILE_ROWS  = 2048;                 // = THREADS * 4
static constexpr int TILE_F4    = TILE_ROWS * 3 / 4;    // 1536 = 3*THREADS
static constexpr int TILE_BYTES = TILE_F4 * 16;         // 24576 B per input
static constexpr int GRID_BLOCKS = 148;                 // 1 CTA per SM
static constexpr int MAX_BLOCKS  = 1024;

__device__ float4 g_partials[MAX_BLOCKS];
__device__ unsigned int g_ticket = 0;

__device__ __forceinline__ float rcp_fast(float x) {
    float r; asm("rcp.approx.f32 %0, %1;" : "=f"(r) : "f"(x)); return r;
}
__device__ __forceinline__ float rsqrt_fast(float x) {
    float r; asm("rsqrt.approx.f32 %0, %1;" : "=f"(r) : "f"(x)); return r;
}
__device__ __forceinline__ uint32_t smem_u32(const void* p) {
    uint32_t a;
    asm("{ .reg .u64 t; cvta.to.shared.u64 t, %1; cvt.u32.u64 %0, t; }"
        : "=r"(a) : "l"(p));
    return a;
}
__device__ __forceinline__ void mbar_init(uint32_t mbar, uint32_t count) {
    asm volatile("mbarrier.init.shared.b64 [%0], %1;" :: "r"(mbar), "r"(count) : "memory");
}
__device__ __forceinline__ void mbar_expect_tx(uint32_t mbar, uint32_t bytes) {
    asm volatile("mbarrier.arrive.expect_tx.shared.b64 _, [%0], %1;"
                 :: "r"(mbar), "r"(bytes) : "memory");
}
__device__ __forceinline__ void mbar_wait(uint32_t mbar, uint32_t parity) {
    uint32_t done;
    asm volatile(
        "{\n\t.reg .pred p;\n\t"
        "mbarrier.try_wait.parity.acquire.cta.shared::cta.b64 p, [%1], %2;\n\t"
        "selp.b32 %0, 1, 0, p;\n\t}"
        : "=r"(done) : "r"(mbar), "r"(parity) : "memory");
    if (!done) {
        asm volatile(
            "{\n\t.reg .pred P1;\n\t"
            "W_%=:\n\t"
            "mbarrier.try_wait.parity.acquire.cta.shared::cta.b64 P1, [%0], %1, 0x989680;\n\t"
            "@P1 bra.uni D_%=;\n\t"
            "bra.uni W_%=;\n\t"
            "D_%=:\n\t}"
            :: "r"(mbar), "r"(parity) : "memory");
    }
}
__device__ __forceinline__ void bulk_g2s(uint32_t dst_smem, const void* src_gmem,
                                         uint32_t bytes, uint32_t mbar) {
    asm volatile(
        "cp.async.bulk.shared::cluster.global.mbarrier::complete_tx::bytes "
        "[%0], [%1], %2, [%3];"
        :: "r"(dst_smem), "l"(src_gmem), "r"(bytes), "r"(mbar) : "memory");
}

__device__ __forceinline__ void process_row(
    float ax, float ay, float az,
    float bx, float by, float bz,
    float& sx, float& sy, float& sz, float& cnt)
{
    float r1 = fmaf(ax, ax, fmaf(ay, ay, az * az));
    float r2 = fmaf(bx, bx, fmaf(by, by, bz * bz));
    float d  = fmaf(ax, bx, fmaf(ay, by, az * bz));
    float SA = ax + ay + az;
    float SB = bx + by + bz;

    float m = (r1 > 1e-16f) ? 1.0f : 0.0f;   // mask: ||v1|| > 1e-8

    float inv12 = rsqrt_fast(fmaf(r1, r2, 1e-37f));
    float c = d * inv12;
    c = fminf(1.0f, fmaxf(-1.0f, c));
    float w = c - 1.0f;

    float g = inv12 * inv12 * r2;            // 1/r1
    float e = d * g;
    float f = fmaf(-SA, e, SB);
    float D = fmaf(-d, e, r2) + 1e-30f;      // r2*sin^2 + tiny
    float fi = f * rcp_fast(D);

    float cA  = w * fmaf(-e, fi, SA * g);
    float cB  = w * fi;
    float cAt = -SB * inv12;
    float cBt =  SA * inv12;

    float tax = fmaf(ax, cAt, bx * cBt);
    float tbx = fmaf(ax, cA,  bx * cB);
    float tay = fmaf(ay, cAt, by * cBt);
    float tby = fmaf(ay, cA,  by * cB);
    float taz = fmaf(az, cAt, bz * cBt);
    float tbz = fmaf(az, cA,  bz * cB);

    sx = fmaf(m, fmaf(ALPHA, tax * tax, BETTA * tbx * tbx), sx);
    sy = fmaf(m, fmaf(ALPHA, tay * tay, BETTA * tby * tby), sy);
    sz = fmaf(m, fmaf(ALPHA, taz * taz, BETTA * tbz * tbz), sz);
    cnt += m;
}

__device__ __forceinline__ void block_reduce(
    float sx, float sy, float sz, float cnt, float4* result)
{
    #pragma unroll
    for (int o = 16; o > 0; o >>= 1) {
        sx  += __shfl_down_sync(0xffffffffu, sx,  o);
        sy  += __shfl_down_sync(0xffffffffu, sy,  o);
        sz  += __shfl_down_sync(0xffffffffu, sz,  o);
        cnt += __shfl_down_sync(0xffffffffu, cnt, o);
    }
    __shared__ float4 rsm[THREADS / 32];
    int lane = threadIdx.x & 31;
    int warp = threadIdx.x >> 5;
    if (lane == 0) rsm[warp] = make_float4(sx, sy, sz, cnt);
    __syncthreads();
    if (warp == 0) {
        float4 v = (lane < (blockDim.x >> 5)) ? rsm[lane]
                                              : make_float4(0.f, 0.f, 0.f, 0.f);
        sx = v.x; sy = v.y; sz = v.z; cnt = v.w;
        #pragma unroll
        for (int o = 16; o > 0; o >>= 1) {
            sx  += __shfl_down_sync(0xffffffffu, sx,  o);
            sy  += __shfl_down_sync(0xffffffffu, sy,  o);
            sz  += __shfl_down_sync(0xffffffffu, sz,  o);
            cnt += __shfl_down_sync(0xffffffffu, cnt, o);
        }
        if (lane == 0) *result = make_float4(sx, sy, sz, cnt);
    }
    __syncthreads();
}

__device__ __forceinline__ float fix_num(float x) {
    if (isnan(x)) return 0.0f;
    if (isinf(x)) return x > 0.0f ? 0.1f : -0.1f;
    return x;
}

extern __shared__ unsigned char dynsmem[];

__global__ __launch_bounds__(THREADS)
void trl_deep_kernel(const float* __restrict__ v1,
                     const float* __restrict__ v2,
                     float* __restrict__ out,
                     int rows)
{
    float4* sA = reinterpret_cast<float4*>(dynsmem);           // STAGES*1536
    float4* sB = sA + STAGES * TILE_F4;
    uint64_t* mbar = reinterpret_cast<uint64_t*>(sB + STAGES * TILE_F4);

    const int tid = threadIdx.x;
    const int b   = blockIdx.x;
    const int G   = gridDim.x;

    uint32_t mbar_addr[STAGES];
    #pragma unroll
    for (int s = 0; s < STAGES; s++) mbar_addr[s] = smem_u32(&mbar[s]);
    if (tid == 0) {
        #pragma unroll
        for (int s = 0; s < STAGES; s++) mbar_init(mbar_addr[s], 1);
    }
    __syncthreads();

    float sx = 0.f, sy = 0.f, sz = 0.f, cnt = 0.f;

    const int tiles = rows / TILE_ROWS;
    const int n_my = (tiles > b) ? ((tiles - 1 - b) / G + 1) : 0;

    if (tid == 0) {
        int prol = n_my < STAGES ? n_my : STAGES;
        for (int p = 0; p < prol; p++) {
            long t = (long)b + (long)p * G;
            mbar_expect_tx(mbar_addr[p], 2 * TILE_BYTES);
            bulk_g2s(smem_u32(sA + p * TILE_F4), v1 + t * (TILE_ROWS * 3),
                     TILE_BYTES, mbar_addr[p]);
            bulk_g2s(smem_u32(sB + p * TILE_F4), v2 + t * (TILE_ROWS * 3),
                     TILE_BYTES, mbar_addr[p]);
        }
    }

    int s = 0;
    uint32_t parity = 0;
    for (int i = 0; i < n_my; i++) {
        mbar_wait(mbar_addr[s], parity);

        // One 4-row group per thread: 6 LDS.128 (conflict-free 3*tid+k),
        // then free the slot immediately and refill before the math.
        const float4* A = sA + s * TILE_F4;
        const float4* B = sB + s * TILE_F4;
        float4 A0 = A[3 * tid + 0];
        float4 A1 = A[3 * tid + 1];
        float4 A2 = A[3 * tid + 2];
        float4 B0 = B[3 * tid + 0];
        float4 B1 = B[3 * tid + 1];
        float4 B2 = B[3 * tid + 2];
        __syncthreads();                // slot drained — refill can start

        if (tid == 0 && i + STAGES < n_my) {
            long t = (long)b + (long)(i + STAGES) * G;
            mbar_expect_tx(mbar_addr[s], 2 * TILE_BYTES);
            bulk_g2s(smem_u32(sA + s * TILE_F4), v1 + t * (TILE_ROWS * 3),
                     TILE_BYTES, mbar_addr[s]);
            bulk_g2s(smem_u32(sB + s * TILE_F4), v2 + t * (TILE_ROWS * 3),
                     TILE_BYTES, mbar_addr[s]);
        }

        process_row(A0.x, A0.y, A0.z, B0.x, B0.y, B0.z, sx, sy, sz, cnt);
        process_row(A0.w, A1.x, A1.y, B0.w, B1.x, B1.y, sx, sy, sz, cnt);
        process_row(A1.z, A1.w, A2.x, B1.z, B1.w, B2.x, sx, sy, sz, cnt);
        process_row(A2.y, A2.z, A2.w, B2.y, B2.z, B2.w, sx, sy, sz, cnt);

        if (++s == STAGES) { s = 0; parity ^= 1u; }
    }

    // Tail rows (rows % TILE_ROWS), coalesced float4 groups across all CTAs.
    {
        const long row0 = (long)tiles * TILE_ROWS;
        const long ngroups = (rows - row0) >> 2;
        const long base_f4 = row0 * 3 / 4;
        const float4* __restrict__ a4 = reinterpret_cast<const float4*>(v1);
        const float4* __restrict__ b4 = reinterpret_cast<const float4*>(v2);
        const long stride = (long)G * THREADS;
        for (long g = (long)b * THREADS + tid; g < ngroups; g += stride) {
            long f = base_f4 + 3 * g;
            float4 a0 = a4[f + 0], a1 = a4[f + 1], a2 = a4[f + 2];
            float4 b0 = b4[f + 0], b1 = b4[f + 1], b2 = b4[f + 2];
            process_row(a0.x, a0.y, a0.z, b0.x, b0.y, b0.z, sx, sy, sz, cnt);
            process_row(a0.w, a1.x, a1.y, b0.w, b1.x, b1.y, sx, sy, sz, cnt);
            process_row(a1.z, a1.w, a2.x, b1.z, b1.w, b2.x, sx, sy, sz, cnt);
            process_row(a2.y, a2.z, a2.w, b2.y, b2.z, b2.w, sx, sy, sz, cnt);
        }
        for (long r = row0 + (ngroups << 2) + (long)b * THREADS + tid;
             r < rows; r += stride) {
            process_row(v1[3 * r], v1[3 * r + 1], v1[3 * r + 2],
                        v2[3 * r], v2[3 * r + 1], v2[3 * r + 2],
                        sx, sy, sz, cnt);
        }
    }

    __shared__ float4 result;
    block_reduce(sx, sy, sz, cnt, &result);

    __shared__ bool is_last;
    if (tid == 0) {
        g_partials[blockIdx.x] = result;
        __threadfence();
        unsigned int tk = atomicAdd(&g_ticket, 1u);
        is_last = (tk == gridDim.x - 1);
    }
    __syncthreads();

    if (is_last) {
        float fx = 0.f, fy = 0.f, fz = 0.f, fc = 0.f;
        for (int i = tid; i < (int)gridDim.x; i += blockDim.x) {
            float4 p;
            const float4* src = &g_partials[i];
            asm volatile("ld.global.cg.v4.f32 {%0,%1,%2,%3}, [%4];"
                         : "=f"(p.x), "=f"(p.y), "=f"(p.z), "=f"(p.w)
                         : "l"(src));
            fx += p.x; fy += p.y; fz += p.z; fc += p.w;
        }
        __shared__ float4 final_r;
        block_reduce(fx, fy, fz, fc, &final_r);
        if (tid == 0) {
            float inv = 1.0f / fmaxf(final_r.w, 1.0f);
            out[0] = fix_num(final_r.x * inv);
            out[1] = fix_num(final_r.y * inv);
            out[2] = fix_num(final_r.z * inv);
            g_ticket = 0;   // reset for graph replay
        }
    }
}

extern "C" void kernel_launch(void* const* d_in, const int* in_sizes, int n_in,
                              void* d_out, int out_size)
{
    const float* v1 = (const float*)d_in[0];
    const float* v2 = (const float*)d_in[1];
    float* out = (float*)d_out;

    int rows = in_sizes[0] / 3;

    size_t shmem = (size_t)STAGES * 2 * TILE_F4 * sizeof(float4)
                 + STAGES * sizeof(uint64_t) + 16;       // ~196.7 KB
    cudaFuncSetAttribute(trl_deep_kernel,
                         cudaFuncAttributeMaxDynamicSharedMemorySize,
                         (int)shmem);

    trl_deep_kernel<<<GRID_BLOCKS, THREADS, shmem>>>(v1, v2, out, rows);
}

// round 15
// speedup vs baseline: 1.0467x; 1.0467x over previous
#include <cuda_runtime.h>
#include <math.h>
#include <stdint.h>

// TransformationRotationLoss — FINAL: persistent CTAs + cp.async.bulk pipeline.
// Best-measured configuration (R11, 14.816us): 296 CTAs (2/SM) x 256 threads,
// 2 stages of 2048-row (24.5KB/input) interleaved tiles, conflict-free LDS
// consume, fused last-block finalize. Warm-state runs at the LTS feed ceiling
// (~3.54 TB/s at benchmark operating clock) — confirmed roofline across 14
// structural variants.
//   u_ta = (SA*b - SB*a) * rsqrt(r1*r2)
//   u_tb = (c-1)*( a*(SA/r1 - e*f/D) + b*(f/D) ), e=d/r1, f=SB-SA*e, D=r2-d*e

#define ALPHA 0.7f
#define BETTA 0.3f

static constexpr int THREADS    = 256;
static constexpr int STAGES     = 2;
static constexpr int TILE_ROWS  = 2048;
static constexpr int TILE_F4    = TILE_ROWS * 3 / 4;    // 1536 float4 per input
static constexpr int HALF_F4    = TILE_F4 / 2;          // 768 (= THREADS*3)
static constexpr int TILE_BYTES = TILE_F4 * 16;         // 24576 B per input
static constexpr int GRID_BLOCKS = 296;                 // 148 SMs * 2 CTAs
static constexpr int MAX_BLOCKS  = 1024;

__device__ float4 g_partials[MAX_BLOCKS];
__device__ unsigned int g_ticket = 0;

__device__ __forceinline__ float rcp_fast(float x) {
    float r; asm("rcp.approx.f32 %0, %1;" : "=f"(r) : "f"(x)); return r;
}
__device__ __forceinline__ float rsqrt_fast(float x) {
    float r; asm("rsqrt.approx.f32 %0, %1;" : "=f"(r) : "f"(x)); return r;
}
__device__ __forceinline__ uint32_t smem_u32(const void* p) {
    uint32_t a;
    asm("{ .reg .u64 t; cvta.to.shared.u64 t, %1; cvt.u32.u64 %0, t; }"
        : "=r"(a) : "l"(p));
    return a;
}
__device__ __forceinline__ void mbar_init(uint32_t mbar, uint32_t count) {
    asm volatile("mbarrier.init.shared.b64 [%0], %1;" :: "r"(mbar), "r"(count) : "memory");
}
__device__ __forceinline__ void mbar_expect_tx(uint32_t mbar, uint32_t bytes) {
    asm volatile("mbarrier.arrive.expect_tx.shared.b64 _, [%0], %1;"
                 :: "r"(mbar), "r"(bytes) : "memory");
}
__device__ __forceinline__ void mbar_wait(uint32_t mbar, uint32_t parity) {
    uint32_t done;
    asm volatile(
        "{\n\t.reg .pred p;\n\t"
        "mbarrier.try_wait.parity.acquire.cta.shared::cta.b64 p, [%1], %2;\n\t"
        "selp.b32 %0, 1, 0, p;\n\t}"
        : "=r"(done) : "r"(mbar), "r"(parity) : "memory");
    if (!done) {
        asm volatile(
            "{\n\t.reg .pred P1;\n\t"
            "W_%=:\n\t"
            "mbarrier.try_wait.parity.acquire.cta.shared::cta.b64 P1, [%0], %1, 0x989680;\n\t"
            "@P1 bra.uni D_%=;\n\t"
            "bra.uni W_%=;\n\t"
            "D_%=:\n\t}"
            :: "r"(mbar), "r"(parity) : "memory");
    }
}
__device__ __forceinline__ void bulk_g2s(uint32_t dst_smem, const void* src_gmem,
                                         uint32_t bytes, uint32_t mbar) {
    asm volatile(
        "cp.async.bulk.shared::cluster.global.mbarrier::complete_tx::bytes "
        "[%0], [%1], %2, [%3];"
        :: "r"(dst_smem), "l"(src_gmem), "r"(bytes), "r"(mbar) : "memory");
}

__device__ __forceinline__ void process_row(
    float ax, float ay, float az,
    float bx, float by, float bz,
    float& sx, float& sy, float& sz, float& cnt)
{
    float r1 = fmaf(ax, ax, fmaf(ay, ay, az * az));
    float r2 = fmaf(bx, bx, fmaf(by, by, bz * bz));
    float d  = fmaf(ax, bx, fmaf(ay, by, az * bz));
    float SA = ax + ay + az;
    float SB = bx + by + bz;

    float m = (r1 > 1e-16f) ? 1.0f : 0.0f;   // mask: ||v1|| > 1e-8

    float inv12 = rsqrt_fast(fmaf(r1, r2, 1e-37f));
    float c = d * inv12;
    c = fminf(1.0f, fmaxf(-1.0f, c));
    float w = c - 1.0f;

    float g = inv12 * inv12 * r2;            // 1/r1
    float e = d * g;
    float f = fmaf(-SA, e, SB);
    float D = fmaf(-d, e, r2) + 1e-30f;      // r2*sin^2 + tiny
    float fi = f * rcp_fast(D);

    float cA  = w * fmaf(-e, fi, SA * g);
    float cB  = w * fi;
    float cAt = -SB * inv12;
    float cBt =  SA * inv12;

    float tax = fmaf(ax, cAt, bx * cBt);
    float tbx = fmaf(ax, cA,  bx * cB);
    float tay = fmaf(ay, cAt, by * cBt);
    float tby = fmaf(ay, cA,  by * cB);
    float taz = fmaf(az, cAt, bz * cBt);
    float tbz = fmaf(az, cA,  bz * cB);

    sx = fmaf(m, fmaf(ALPHA, tax * tax, BETTA * tbx * tbx), sx);
    sy = fmaf(m, fmaf(ALPHA, tay * tay, BETTA * tby * tby), sy);
    sz = fmaf(m, fmaf(ALPHA, taz * taz, BETTA * tbz * tbz), sz);
    cnt += m;
}

// Consume a 1024-row half-tile (768 float4 per input) with the conflict-free
// 3*tid+k LDS.128 pattern; 4 rows per thread.
__device__ __forceinline__ void consume_half(
    const float4* __restrict__ A, const float4* __restrict__ B, int tid,
    float& sx, float& sy, float& sz, float& cnt)
{
    float4 A0 = A[3 * tid + 0];
    float4 A1 = A[3 * tid + 1];
    float4 A2 = A[3 * tid + 2];
    float4 B0 = B[3 * tid + 0];
    float4 B1 = B[3 * tid + 1];
    float4 B2 = B[3 * tid + 2];

    process_row(A0.x, A0.y, A0.z, B0.x, B0.y, B0.z, sx, sy, sz, cnt);
    process_row(A0.w, A1.x, A1.y, B0.w, B1.x, B1.y, sx, sy, sz, cnt);
    process_row(A1.z, A1.w, A2.x, B1.z, B1.w, B2.x, sx, sy, sz, cnt);
    process_row(A2.y, A2.z, A2.w, B2.y, B2.z, B2.w, sx, sy, sz, cnt);
}

__device__ __forceinline__ void block_reduce(
    float sx, float sy, float sz, float cnt, float4* result)
{
    #pragma unroll
    for (int o = 16; o > 0; o >>= 1) {
        sx  += __shfl_down_sync(0xffffffffu, sx,  o);
        sy  += __shfl_down_sync(0xffffffffu, sy,  o);
        sz  += __shfl_down_sync(0xffffffffu, sz,  o);
        cnt += __shfl_down_sync(0xffffffffu, cnt, o);
    }
    __shared__ float4 rsm[THREADS / 32];
    int lane = threadIdx.x & 31;
    int warp = threadIdx.x >> 5;
    if (lane == 0) rsm[warp] = make_float4(sx, sy, sz, cnt);
    __syncthreads();
    if (warp == 0) {
        float4 v = (lane < (blockDim.x >> 5)) ? rsm[lane]
                                              : make_float4(0.f, 0.f, 0.f, 0.f);
        sx = v.x; sy = v.y; sz = v.z; cnt = v.w;
        #pragma unroll
        for (int o = 16; o > 0; o >>= 1) {
            sx  += __shfl_down_sync(0xffffffffu, sx,  o);
            sy  += __shfl_down_sync(0xffffffffu, sy,  o);
            sz  += __shfl_down_sync(0xffffffffu, sz,  o);
            cnt += __shfl_down_sync(0xffffffffu, cnt, o);
        }
        if (lane == 0) *result = make_float4(sx, sy, sz, cnt);
    }
    __syncthreads();
}

__device__ __forceinline__ float fix_num(float x) {
    if (isnan(x)) return 0.0f;
    if (isinf(x)) return x > 0.0f ? 0.1f : -0.1f;
    return x;
}

extern __shared__ unsigned char dynsmem[];

__global__ __launch_bounds__(THREADS)
void trl_bigtile_kernel(const float* __restrict__ v1,
                        const float* __restrict__ v2,
                        float* __restrict__ out,
                        int rows)
{
    float4* sA = reinterpret_cast<float4*>(dynsmem);           // STAGES*1536
    float4* sB = sA + STAGES * TILE_F4;
    uint64_t* mbar = reinterpret_cast<uint64_t*>(sB + STAGES * TILE_F4);

    const int tid = threadIdx.x;
    const int b   = blockIdx.x;
    const int G   = gridDim.x;

    uint32_t mbar_addr[STAGES];
    #pragma unroll
    for (int s = 0; s < STAGES; s++) mbar_addr[s] = smem_u32(&mbar[s]);
    if (tid == 0) {
        #pragma unroll
        for (int s = 0; s < STAGES; s++) mbar_init(mbar_addr[s], 1);
    }
    __syncthreads();

    float sx = 0.f, sy = 0.f, sz = 0.f, cnt = 0.f;

    const int tiles = rows / TILE_ROWS;
    const int n_my = (tiles > b) ? ((tiles - 1 - b) / G + 1) : 0;

    if (tid == 0) {
        int prol = n_my < STAGES ? n_my : STAGES;
        for (int p = 0; p < prol; p++) {
            long t = (long)b + (long)p * G;
            mbar_expect_tx(mbar_addr[p], 2 * TILE_BYTES);
            bulk_g2s(smem_u32(sA + p * TILE_F4), v1 + t * (TILE_ROWS * 3),
                     TILE_BYTES, mbar_addr[p]);
            bulk_g2s(smem_u32(sB + p * TILE_F4), v2 + t * (TILE_ROWS * 3),
                     TILE_BYTES, mbar_addr[p]);
        }
    }

    int s = 0;
    uint32_t parity = 0;
    for (int i = 0; i < n_my; i++) {
        mbar_wait(mbar_addr[s], parity);

        const float4* A = sA + s * TILE_F4;
        const float4* B = sB + s * TILE_F4;

        // Half 0 (rows 0..1023 of the tile)
        consume_half(A, B, tid, sx, sy, sz, cnt);
        // Half 1 (rows 1024..2047)
        consume_half(A + HALF_F4, B + HALF_F4, tid, sx, sy, sz, cnt);

        __syncthreads();                // whole slot consumed, free for refill
        if (tid == 0 && i + STAGES < n_my) {
            long t = (long)b + (long)(i + STAGES) * G;
            mbar_expect_tx(mbar_addr[s], 2 * TILE_BYTES);
            bulk_g2s(smem_u32(sA + s * TILE_F4), v1 + t * (TILE_ROWS * 3),
                     TILE_BYTES, mbar_addr[s]);
            bulk_g2s(smem_u32(sB + s * TILE_F4), v2 + t * (TILE_ROWS * 3),
                     TILE_BYTES, mbar_addr[s]);
        }

        if (++s == STAGES) { s = 0; parity ^= 1u; }
    }

    // Tail rows (rows % TILE_ROWS), coalesced float4 groups across all CTAs.
    {
        const long row0 = (long)tiles * TILE_ROWS;
        const long ngroups = (rows - row0) >> 2;
        const long base_f4 = row0 * 3 / 4;
        const float4* __restrict__ a4 = reinterpret_cast<const float4*>(v1);
        const float4* __restrict__ b4 = reinterpret_cast<const float4*>(v2);
        const long stride = (long)G * THREADS;
        for (long g = (long)b * THREADS + tid; g < ngroups; g += stride) {
            long f = base_f4 + 3 * g;
            float4 a0 = a4[f + 0], a1 = a4[f + 1], a2 = a4[f + 2];
            float4 b0 = b4[f + 0], b1 = b4[f + 1], b2 = b4[f + 2];
            process_row(a0.x, a0.y, a0.z, b0.x, b0.y, b0.z, sx, sy, sz, cnt);
            process_row(a0.w, a1.x, a1.y, b0.w, b1.x, b1.y, sx, sy, sz, cnt);
            process_row(a1.z, a1.w, a2.x, b1.z, b1.w, b2.x, sx, sy, sz, cnt);
            process_row(a2.y, a2.z, a2.w, b2.y, b2.z, b2.w, sx, sy, sz, cnt);
        }
        for (long r = row0 + (ngroups << 2) + (long)b * THREADS + tid;
             r < rows; r += stride) {
            process_row(v1[3 * r], v1[3 * r + 1], v1[3 * r + 2],
                        v2[3 * r], v2[3 * r + 1], v2[3 * r + 2],
                        sx, sy, sz, cnt);
        }
    }

    __shared__ float4 result;
    block_reduce(sx, sy, sz, cnt, &result);

    __shared__ bool is_last;
    if (tid == 0) {
        g_partials[blockIdx.x] = result;
        __threadfence();
        unsigned int tk = atomicAdd(&g_ticket, 1u);
        is_last = (tk == gridDim.x - 1);
    }
    __syncthreads();

    if (is_last) {
        float fx = 0.f, fy = 0.f, fz = 0.f, fc = 0.f;
        for (int i = tid; i < (int)gridDim.x; i += blockDim.x) {
            float4 p;
            const float4* src = &g_partials[i];
            asm volatile("ld.global.cg.v4.f32 {%0,%1,%2,%3}, [%4];"
                         : "=f"(p.x), "=f"(p.y), "=f"(p.z), "=f"(p.w)
                         : "l"(src));
            fx += p.x; fy += p.y; fz += p.z; fc += p.w;
        }
        __shared__ float4 final_r;
        block_reduce(fx, fy, fz, fc, &final_r);
        if (tid == 0) {
            float inv = 1.0f / fmaxf(final_r.w, 1.0f);
            out[0] = fix_num(final_r.x * inv);
            out[1] = fix_num(final_r.y * inv);
            out[2] = fix_num(final_r.z * inv);
            g_ticket = 0;   // reset for graph replay
        }
    }
}

extern "C" void kernel_launch(void* const* d_in, const int* in_sizes, int n_in,
                              void* d_out, int out_size)
{
    const float* v1 = (const float*)d_in[0];
    const float* v2 = (const float*)d_in[1];
    float* out = (float*)d_out;

    int rows = in_sizes[0] / 3;

    size_t shmem = (size_t)STAGES * 2 * TILE_F4 * sizeof(float4)
                 + STAGES * sizeof(uint64_t) + 16;       // ~98.3 KB
    cudaFuncSetAttribute(trl_bigtile_kernel,
                         cudaFuncAttributeMaxDynamicSharedMemorySize,
                         (int)shmem);

    trl_bigtile_kernel<<<GRID_BLOCKS, THREADS, shmem>>>(v1, v2, out, rows);
}